// round 14
// baseline (speedup 1.0000x reference)
#include <cuda_runtime.h>
#include <cuda_bf16.h>

#define NMAX 100000
#define MAXDEG 64

// ---------------- scratch (allocation-free) ----------------
__device__ float g_m[(size_t)NMAX * 128];
__device__ float g_h[(size_t)NMAX * 128];         // layer-1 h, packed bf16 hi/lo (uint4/4cols)
__device__ int g_counts[NMAX];                    // zero-initialized at load
__device__ int g_slots[(size_t)NMAX * MAXDEG];    // incoming src per node
__device__ unsigned short g_wthi[2][128 * 128];
__device__ unsigned short g_wtlo[2][128 * 128];
__device__ float g_b1p[128];                      // pi-permuted bias for layer 1

__device__ __forceinline__ unsigned smem_u32(const void* p) {
    unsigned a;
    asm("{ .reg .u64 t; cvta.to.shared.u64 t, %1; cvt.u32.u64 %0, t; }" : "=r"(a) : "l"(p));
    return a;
}

// W tile layout: row-major 256B rows (n = 0..127, k bf16 cols); 16B chunks
// XOR-swizzled: chunk' = (k>>3) ^ (n & 7).
__device__ __forceinline__ unsigned tile_off(int row, int k) {
    return (unsigned)(row * 256 + ((((k >> 3) ^ (row & 7))) << 4) + (k & 7) * 2);
}

// sigma^{-1} == pi, applied within each 16-group.
__device__ __forceinline__ int perm16(int w) {
    return (w & 2) ? (8 + ((w >> 2) << 1) + (w & 1))
                   : (((w >> 2) << 1) + (w & 1));
}

// ---------------------------------------------------------------------------
// Fused prep: blocks [0,128) convert W^T to bf16 hi/lo tiles
// (layer 0 with sigma^{-1} k-column mapping, layer 1 standard);
// blocks [128, ...) place edges into the slot table. Block 0 also builds b1p.
// ---------------------------------------------------------------------------
__global__ void prep_kernel(const float* __restrict__ W1, const float* __restrict__ W2,
                            const float* __restrict__ b1,
                            const int* __restrict__ src, const int* __restrict__ dst,
                            int* __restrict__ counts, int* __restrict__ slots, int E) {
    if (blockIdx.x < 128) {
        int id = blockIdx.x * 256 + threadIdx.x;   // 0..32767
        int layer = id >> 14;
        int nn = (id >> 7) & 127;
        int k = id & 127;
        const float* W = layer ? W2 : W1;
        float v = W[k * 128 + nn];                 // W^T[n][k]
        __nv_bfloat16 h = __float2bfloat16(v);
        __nv_bfloat16 l = __float2bfloat16(v - __bfloat162float(h));
        int kd = k;
        if (layer == 0) kd = (k & ~15) | perm16(k & 15);   // sigma^{-1} col map
        unsigned idx = tile_off(nn, kd) >> 1;
        g_wthi[layer][idx] = *reinterpret_cast<unsigned short*>(&h);
        g_wtlo[layer][idx] = *reinterpret_cast<unsigned short*>(&l);
        if (blockIdx.x == 0 && threadIdx.x < 128) {
            int q = threadIdx.x;
            g_b1p[q] = b1[(q & ~15) | perm16(q & 15)];     // b1[pi(q)]
        }
    } else {
        int e = (blockIdx.x - 128) * 256 + threadIdx.x;
        if (e < E) {
            int d = dst[e];
            int pos = atomicAdd(&counts[d], 1);
            if (pos < MAXDEG) slots[(size_t)d * MAXDEG + pos] = src[e];
        }
    }
}

// ---------------------------------------------------------------------------
// Warp-autonomous persistent GEMM (R11 geometry): C = A_eff @ W
// Grid 296 x 256 thr (2 CTA/SM). W hi/lo resident in smem (64KB).
// Each WARP owns 16-row x 128-col tiles.
// PACKED=0: A is fp32; 2x LDG.128 per k16 (sigma ordering, compensated in W
//           prep); split to bf16 hi/lo in-kernel; optional relu.
// PACKED=1: A is pre-split packed bf16 (uint4 = hi01,hi23,lo01,lo23 per 4
//           cols); fragments load directly, zero conversion ALU.
// permuteStore=1 -> pi-ordered STG.128 (layer 1 m); =0 -> standard (layer 2).
// 3 products: Ah*Wh + Ah*Wl + Al*Wh, fp32 accum. No syncs in main loop.
// ---------------------------------------------------------------------------
#define WHI 0
#define WLO 32768
#define GEMM_SMEM 65536

#define MMA_OP(cc, A0, A1, A2, A3, B0, B1)                                       \
    asm volatile("mma.sync.aligned.m16n8k16.row.col.f32.bf16.bf16.f32 "          \
                 "{%0,%1,%2,%3}, {%4,%5,%6,%7}, {%8,%9}, {%0,%1,%2,%3};"         \
                 : "+f"((cc)[0]), "+f"((cc)[1]), "+f"((cc)[2]), "+f"((cc)[3])    \
                 : "r"(A0), "r"(A1), "r"(A2), "r"(A3), "r"(B0), "r"(B1))

__device__ __forceinline__ void split2(float x, float y, unsigned& hi, unsigned& lo) {
    __nv_bfloat162 h = __floats2bfloat162_rn(x, y);
    float2 f = __bfloat1622float2(h);
    __nv_bfloat162 l = __floats2bfloat162_rn(x - f.x, y - f.y);
    hi = *reinterpret_cast<unsigned*>(&h);
    lo = *reinterpret_cast<unsigned*>(&l);
}

template <int PACKED>
__global__ __launch_bounds__(256, 2) void gemm_mma(
    const void* __restrict__ Ain, const unsigned short* __restrict__ Whi,
    const unsigned short* __restrict__ Wlo, float* __restrict__ C,
    int N, int applyRelu, int numTiles, int permuteStore) {
    extern __shared__ __align__(128) char smem[];
    const unsigned sb = smem_u32(smem);
    const int tx = threadIdx.x;
    const int lane = tx & 31;

    // Load W hi/lo once (2048 uint4 each).
    {
        const uint4* wh = (const uint4*)Whi;
        const uint4* wl = (const uint4*)Wlo;
        uint4* sh = (uint4*)(smem + WHI);
        uint4* sl = (uint4*)(smem + WLO);
#pragma unroll
        for (int i = 0; i < 8; i++) {
            sh[tx + 256 * i] = wh[tx + 256 * i];
            sl[tx + 256 * i] = wl[tx + 256 * i];
        }
    }
    __syncthreads();   // only sync: W resident for the whole kernel

    const int b_row_l = ((lane >> 4) << 3) + (lane & 7);
    const int b_half = (lane >> 3) & 1;
    const int sw_b = b_row_l & 7;

    const int ar = lane >> 2;        // row within m16 (and +8)
    const int ac = lane & 3;         // 16B col within k16 chunk

    const int warpGlobal = (blockIdx.x * 8) + (tx >> 5);
    const int totalWarps = gridDim.x * 8;
    const float4* A4 = (const float4*)Ain;
    const uint4* HP4 = (const uint4*)Ain;

    for (int tile = warpGlobal; tile < numTiles; tile += totalWarps) {
        const int row0 = tile * 16;
        const int r0 = row0 + ar;
        const int r1 = r0 + 8;

        float c[8][8];
#pragma unroll
        for (int j = 0; j < 8; j++)
#pragma unroll
            for (int q = 0; q < 8; q++) c[j][q] = 0.f;

#pragma unroll
        for (int kk = 0; kk < 8; kk++) {
            unsigned ah0, al0, ah1, al1, ah2, al2, ah3, al3;
            if (PACKED) {
                uint4 u0 = make_uint4(0u, 0u, 0u, 0u), u1 = u0;
                if (r0 < N) u0 = __ldg(&HP4[(size_t)r0 * 32 + kk * 4 + ac]);
                if (r1 < N) u1 = __ldg(&HP4[(size_t)r1 * 32 + kk * 4 + ac]);
                ah0 = u0.x; ah2 = u0.y; al0 = u0.z; al2 = u0.w;
                ah1 = u1.x; ah3 = u1.y; al1 = u1.z; al3 = u1.w;
            } else {
                float4 v0 = make_float4(0.f, 0.f, 0.f, 0.f), v1 = v0;
                if (r0 < N) v0 = __ldg(&A4[(size_t)r0 * 32 + kk * 4 + ac]);
                if (r1 < N) v1 = __ldg(&A4[(size_t)r1 * 32 + kk * 4 + ac]);
                if (applyRelu) {
                    v0.x = fmaxf(v0.x, 0.f); v0.y = fmaxf(v0.y, 0.f);
                    v0.z = fmaxf(v0.z, 0.f); v0.w = fmaxf(v0.w, 0.f);
                    v1.x = fmaxf(v1.x, 0.f); v1.y = fmaxf(v1.y, 0.f);
                    v1.z = fmaxf(v1.z, 0.f); v1.w = fmaxf(v1.w, 0.f);
                }
                // Frag assignment under sigma: a0<-v0.xy, a1<-v1.xy, a2<-v0.zw, a3<-v1.zw
                split2(v0.x, v0.y, ah0, al0);
                split2(v1.x, v1.y, ah1, al1);
                split2(v0.z, v0.w, ah2, al2);
                split2(v1.z, v1.w, ah3, al3);
            }

            const unsigned kchunk = (unsigned)(((kk * 2 + b_half) ^ sw_b) << 4);
#pragma unroll
            for (int j = 0; j < 8; j++) {        // n16 groups
                const unsigned roff = (unsigned)((j * 16 + b_row_l) * 256) + kchunk;
                unsigned wh0, wh1, wh2, wh3, wl0, wl1, wl2, wl3;
                asm volatile("ldmatrix.sync.aligned.m8n8.x4.shared.b16 {%0,%1,%2,%3}, [%4];"
                             : "=r"(wh0), "=r"(wh1), "=r"(wh2), "=r"(wh3)
                             : "r"(sb + WHI + roff));
                asm volatile("ldmatrix.sync.aligned.m8n8.x4.shared.b16 {%0,%1,%2,%3}, [%4];"
                             : "=r"(wl0), "=r"(wl1), "=r"(wl2), "=r"(wl3)
                             : "r"(sb + WLO + roff));
                MMA_OP(c[j] + 0, ah0, ah1, ah2, ah3, wh0, wh1);
                MMA_OP(c[j] + 4, ah0, ah1, ah2, ah3, wh2, wh3);
                MMA_OP(c[j] + 0, al0, al1, al2, al3, wh0, wh1);
                MMA_OP(c[j] + 4, al0, al1, al2, al3, wh2, wh3);
                MMA_OP(c[j] + 0, ah0, ah1, ah2, ah3, wl0, wl1);
                MMA_OP(c[j] + 4, ah0, ah1, ah2, ah3, wl2, wl3);
            }
        }

        if (permuteStore) {
            // pi-permuted column order: one STG.128 per j per row.
            if (r0 < N) {
                float4* Crow = (float4*)(C + (size_t)r0 * 128) + (lane & 3);
#pragma unroll
                for (int j = 0; j < 8; j++)
                    Crow[j * 4] = make_float4(c[j][0], c[j][1], c[j][4], c[j][5]);
            }
            if (r1 < N) {
                float4* Crow = (float4*)(C + (size_t)r1 * 128) + (lane & 3);
#pragma unroll
                for (int j = 0; j < 8; j++)
                    Crow[j * 4] = make_float4(c[j][2], c[j][3], c[j][6], c[j][7]);
            }
        } else {
            if (r0 < N) {
                float* Crow = C + (size_t)r0 * 128 + (lane & 3) * 2;
#pragma unroll
                for (int j = 0; j < 8; j++) {
                    *(float2*)(Crow + j * 16) = make_float2(c[j][0], c[j][1]);
                    *(float2*)(Crow + j * 16 + 8) = make_float2(c[j][4], c[j][5]);
                }
            }
            if (r1 < N) {
                float* Crow = C + (size_t)r1 * 128 + (lane & 3) * 2;
#pragma unroll
                for (int j = 0; j < 8; j++) {
                    *(float2*)(Crow + j * 16) = make_float2(c[j][2], c[j][3]);
                    *(float2*)(Crow + j * 16 + 8) = make_float2(c[j][6], c[j][7]);
                }
            }
        }
    }
}

// ---------------------------------------------------------------------------
// Layer-1 aggregation: one warp per node, MLP-4 unroll (R8 gather loop).
// Epilogue: bias + ReLU + bf16 hi/lo split, packed store (uint4 per 4 cols).
// Conversion ALU is free here (kernel is LTS-bound).
// ---------------------------------------------------------------------------
__global__ void aggregate_pack_kernel(const float* __restrict__ m,
                                      const int* __restrict__ counts,
                                      const int* __restrict__ slots,
                                      const float* __restrict__ bias,
                                      uint4* __restrict__ outp, int N) {
    int warp = (blockIdx.x * blockDim.x + threadIdx.x) >> 5;
    int lane = threadIdx.x & 31;
    if (warp >= N) return;
    int cnt = counts[warp];
    if (cnt > MAXDEG) cnt = MAXDEG;
    const int* sl = slots + (size_t)warp * MAXDEG;
    float4 acc = ((const float4*)bias)[lane];
    int idx = 0;
    for (; idx + 4 <= cnt; idx += 4) {
        int s0 = __ldg(&sl[idx]);
        int s1 = __ldg(&sl[idx + 1]);
        int s2 = __ldg(&sl[idx + 2]);
        int s3 = __ldg(&sl[idx + 3]);
        float4 v0 = ((const float4*)(m + (size_t)s0 * 128))[lane];
        float4 v1 = ((const float4*)(m + (size_t)s1 * 128))[lane];
        float4 v2 = ((const float4*)(m + (size_t)s2 * 128))[lane];
        float4 v3 = ((const float4*)(m + (size_t)s3 * 128))[lane];
        acc.x += v0.x + v1.x + v2.x + v3.x;
        acc.y += v0.y + v1.y + v2.y + v3.y;
        acc.z += v0.z + v1.z + v2.z + v3.z;
        acc.w += v0.w + v1.w + v2.w + v3.w;
    }
    for (; idx < cnt; idx++) {
        int s = __ldg(&sl[idx]);
        float4 v = ((const float4*)(m + (size_t)s * 128))[lane];
        acc.x += v.x; acc.y += v.y; acc.z += v.z; acc.w += v.w;
    }
    // ReLU + bf16 hi/lo split + pack.
    acc.x = fmaxf(acc.x, 0.f); acc.y = fmaxf(acc.y, 0.f);
    acc.z = fmaxf(acc.z, 0.f); acc.w = fmaxf(acc.w, 0.f);
    unsigned h01, l01, h23, l23;
    split2(acc.x, acc.y, h01, l01);
    split2(acc.z, acc.w, h23, l23);
    outp[(size_t)warp * 32 + lane] = make_uint4(h01, h23, l01, l23);
}

// ---------------------------------------------------------------------------
// Layer-2 aggregation (R8 version): fp32 out + bias; re-zeroes counts.
// ---------------------------------------------------------------------------
__global__ void aggregate_kernel(const float* __restrict__ m,
                                 int* __restrict__ counts,
                                 const int* __restrict__ slots,
                                 const float* __restrict__ bias,
                                 float* __restrict__ out, int N) {
    int warp = (blockIdx.x * blockDim.x + threadIdx.x) >> 5;
    int lane = threadIdx.x & 31;
    if (warp >= N) return;
    int cnt = counts[warp];
    if (cnt > MAXDEG) cnt = MAXDEG;
    const int* sl = slots + (size_t)warp * MAXDEG;
    float4 acc = ((const float4*)bias)[lane];
    int idx = 0;
    for (; idx + 4 <= cnt; idx += 4) {
        int s0 = __ldg(&sl[idx]);
        int s1 = __ldg(&sl[idx + 1]);
        int s2 = __ldg(&sl[idx + 2]);
        int s3 = __ldg(&sl[idx + 3]);
        float4 v0 = ((const float4*)(m + (size_t)s0 * 128))[lane];
        float4 v1 = ((const float4*)(m + (size_t)s1 * 128))[lane];
        float4 v2 = ((const float4*)(m + (size_t)s2 * 128))[lane];
        float4 v3 = ((const float4*)(m + (size_t)s3 * 128))[lane];
        acc.x += v0.x + v1.x + v2.x + v3.x;
        acc.y += v0.y + v1.y + v2.y + v3.y;
        acc.z += v0.z + v1.z + v2.z + v3.z;
        acc.w += v0.w + v1.w + v2.w + v3.w;
    }
    for (; idx < cnt; idx++) {
        int s = __ldg(&sl[idx]);
        float4 v = ((const float4*)(m + (size_t)s * 128))[lane];
        acc.x += v.x; acc.y += v.y; acc.z += v.z; acc.w += v.w;
    }
    ((float4*)(out + (size_t)warp * 128))[lane] = acc;
    if (lane == 0) counts[warp] = 0;
}

// ---------------------------------------------------------------------------
extern "C" void kernel_launch(void* const* d_in, const int* in_sizes, int n_in,
                              void* d_out, int out_size) {
    const float* x  = (const float*)d_in[0];
    const int*   ei = (const int*)d_in[1];
    const float* W1 = (const float*)d_in[2];
    const float* b1 = (const float*)d_in[3];
    const float* W2 = (const float*)d_in[4];
    const float* b2 = (const float*)d_in[5];
    float* out = (float*)d_out;

    const int N = in_sizes[0] / 128;
    const int E = in_sizes[1] / 2;
    const int* src = ei;
    const int* dst = ei + E;

    float* gm; float* gh;
    int *counts, *slots;
    unsigned short *wthi, *wtlo;
    float* b1p;
    cudaGetSymbolAddress((void**)&gm, g_m);
    cudaGetSymbolAddress((void**)&gh, g_h);
    cudaGetSymbolAddress((void**)&counts, g_counts);
    cudaGetSymbolAddress((void**)&slots, g_slots);
    cudaGetSymbolAddress((void**)&wthi, g_wthi);
    cudaGetSymbolAddress((void**)&wtlo, g_wtlo);
    cudaGetSymbolAddress((void**)&b1p, g_b1p);

    cudaFuncSetAttribute(gemm_mma<0>, cudaFuncAttributeMaxDynamicSharedMemorySize, GEMM_SMEM);
    cudaFuncSetAttribute(gemm_mma<1>, cudaFuncAttributeMaxDynamicSharedMemorySize, GEMM_SMEM);

    const int numTiles = (N + 15) / 16;
    const int gemmGrid = 296;                       // 2 CTA/SM persistent
    const int prepGrid = 128 + (E + 255) / 256;
    const int aggGrid = (N + 7) / 8;

    // Fused prep: W conversion (+sigma^{-1} for W1), b1 perm, slot-table build.
    prep_kernel<<<prepGrid, 256>>>(W1, W2, b1, src, dst, counts, slots, E);

    // Layer 1: m (pi-permuted cols) = x @ W1; h_packed = split(relu(agg(m)+b1p)).
    gemm_mma<0><<<gemmGrid, 256, GEMM_SMEM>>>(x, wthi, wtlo, gm, N, 0, numTiles, 1);
    aggregate_pack_kernel<<<aggGrid, 256>>>(gm, counts, slots, b1p, (uint4*)gh, N);

    // Layer 2: packed-A gemm (frags pre-split; sigma cancels pi), standard store.
    gemm_mma<1><<<gemmGrid, 256, GEMM_SMEM>>>(gh, wthi + 128 * 128, wtlo + 128 * 128, gm, N, 0, numTiles, 0);
    aggregate_kernel<<<aggGrid, 256>>>(gm, counts, slots, b2, out, N);
}

// round 15
// speedup vs baseline: 1.1264x; 1.1264x over previous
#include <cuda_runtime.h>
#include <cuda_bf16.h>

#define NMAX 100000
#define MAXDEG 64

// ---------------- scratch (allocation-free) ----------------
__device__ float g_m[(size_t)NMAX * 128];
__device__ float g_h[(size_t)NMAX * 128];
__device__ int g_counts[NMAX];                    // zero-initialized at load
__device__ int g_slots[(size_t)NMAX * MAXDEG];    // incoming src per node
__device__ unsigned short g_wthi[2][128 * 128];
__device__ unsigned short g_wtlo[2][128 * 128];
__device__ float g_b1p[128];                      // pi-permuted bias for layer 1
__device__ int g_tilectr[2];                      // dynamic tile counters (per layer)

__device__ __forceinline__ unsigned smem_u32(const void* p) {
    unsigned a;
    asm("{ .reg .u64 t; cvta.to.shared.u64 t, %1; cvt.u32.u64 %0, t; }" : "=r"(a) : "l"(p));
    return a;
}

// W tile layout: row-major 256B rows (n = 0..127, k bf16 cols); 16B chunks
// XOR-swizzled: chunk' = (k>>3) ^ (n & 7).
__device__ __forceinline__ unsigned tile_off(int row, int k) {
    return (unsigned)(row * 256 + ((((k >> 3) ^ (row & 7))) << 4) + (k & 7) * 2);
}

// sigma^{-1} == pi, applied within each 16-group.
__device__ __forceinline__ int perm16(int w) {
    return (w & 2) ? (8 + ((w >> 2) << 1) + (w & 1))
                   : (((w >> 2) << 1) + (w & 1));
}

// ---------------------------------------------------------------------------
// Fused prep: blocks [0,128) convert W^T to bf16 hi/lo tiles
// (layer 0 with sigma^{-1} k-column mapping, layer 1 standard);
// blocks [128, ...) place edges into the slot table. Block 0 also builds b1p
// and resets the dynamic tile counters (runs every graph replay).
// ---------------------------------------------------------------------------
__global__ void prep_kernel(const float* __restrict__ W1, const float* __restrict__ W2,
                            const float* __restrict__ b1,
                            const int* __restrict__ src, const int* __restrict__ dst,
                            int* __restrict__ counts, int* __restrict__ slots, int E) {
    if (blockIdx.x < 128) {
        int id = blockIdx.x * 256 + threadIdx.x;   // 0..32767
        int layer = id >> 14;
        int nn = (id >> 7) & 127;
        int k = id & 127;
        const float* W = layer ? W2 : W1;
        float v = W[k * 128 + nn];                 // W^T[n][k]
        __nv_bfloat16 h = __float2bfloat16(v);
        __nv_bfloat16 l = __float2bfloat16(v - __bfloat162float(h));
        int kd = k;
        if (layer == 0) kd = (k & ~15) | perm16(k & 15);   // sigma^{-1} col map
        unsigned idx = tile_off(nn, kd) >> 1;
        g_wthi[layer][idx] = *reinterpret_cast<unsigned short*>(&h);
        g_wtlo[layer][idx] = *reinterpret_cast<unsigned short*>(&l);
        if (blockIdx.x == 0 && threadIdx.x < 128) {
            int q = threadIdx.x;
            g_b1p[q] = b1[(q & ~15) | perm16(q & 15)];     // b1[pi(q)]
        }
        if (blockIdx.x == 0 && threadIdx.x >= 128 && threadIdx.x < 130) {
            g_tilectr[threadIdx.x - 128] = 0;
        }
    } else {
        int e = (blockIdx.x - 128) * 256 + threadIdx.x;
        if (e < E) {
            int d = dst[e];
            int pos = atomicAdd(&counts[d], 1);
            if (pos < MAXDEG) slots[(size_t)d * MAXDEG + pos] = src[e];
        }
    }
}

// ---------------------------------------------------------------------------
// Warp-autonomous persistent GEMM (R11 body): C = (relu?)(A) @ W
// Grid 296 x 256 thr (2 CTA/SM). W hi/lo resident in smem (64KB).
// Each WARP processes 16-row x 128-col tiles, fetched DYNAMICALLY from a
// global atomic counter (removes the 12% static-stride tail imbalance).
// A fragments: 2x LDG.128 per k16 (sigma ordering, compensated in W prep).
// permuteStore=1 -> pi-ordered STG.128 (layer 1 m); =0 -> standard (layer 2).
// 3 products: Ah*Wh + Ah*Wl + Al*Wh, fp32 accum. No syncs in main loop.
// ---------------------------------------------------------------------------
#define WHI 0
#define WLO 32768
#define GEMM_SMEM 65536

#define MMA_OP(cc, A0, A1, A2, A3, B0, B1)                                       \
    asm volatile("mma.sync.aligned.m16n8k16.row.col.f32.bf16.bf16.f32 "          \
                 "{%0,%1,%2,%3}, {%4,%5,%6,%7}, {%8,%9}, {%0,%1,%2,%3};"         \
                 : "+f"((cc)[0]), "+f"((cc)[1]), "+f"((cc)[2]), "+f"((cc)[3])    \
                 : "r"(A0), "r"(A1), "r"(A2), "r"(A3), "r"(B0), "r"(B1))

__device__ __forceinline__ void split2(float x, float y, unsigned& hi, unsigned& lo) {
    __nv_bfloat162 h = __floats2bfloat162_rn(x, y);
    float2 f = __bfloat1622float2(h);
    __nv_bfloat162 l = __floats2bfloat162_rn(x - f.x, y - f.y);
    hi = *reinterpret_cast<unsigned*>(&h);
    lo = *reinterpret_cast<unsigned*>(&l);
}

__global__ __launch_bounds__(256, 2) void gemm_mma(
    const float* __restrict__ A, const unsigned short* __restrict__ Whi,
    const unsigned short* __restrict__ Wlo, float* __restrict__ C,
    int N, int applyRelu, int numTiles, int permuteStore, int* __restrict__ ctr) {
    extern __shared__ __align__(128) char smem[];
    const unsigned sb = smem_u32(smem);
    const int tx = threadIdx.x;
    const int lane = tx & 31;

    // Load W hi/lo once (2048 uint4 each).
    {
        const uint4* wh = (const uint4*)Whi;
        const uint4* wl = (const uint4*)Wlo;
        uint4* sh = (uint4*)(smem + WHI);
        uint4* sl = (uint4*)(smem + WLO);
#pragma unroll
        for (int i = 0; i < 8; i++) {
            sh[tx + 256 * i] = wh[tx + 256 * i];
            sl[tx + 256 * i] = wl[tx + 256 * i];
        }
    }
    __syncthreads();   // only sync: W resident for the whole kernel

    const int b_row_l = ((lane >> 4) << 3) + (lane & 7);
    const int b_half = (lane >> 3) & 1;
    const int sw_b = b_row_l & 7;

    const int ar = lane >> 2;        // row within m16 (and +8)
    const int ac = lane & 3;         // float4 col within k16 chunk

    const float4* A4 = (const float4*)A;

    for (;;) {
        // Dynamic tile fetch: lane 0 grabs, broadcast to warp.
        int tile;
        if (lane == 0) tile = atomicAdd(ctr, 1);
        tile = __shfl_sync(0xFFFFFFFF, tile, 0);
        if (tile >= numTiles) break;

        const int row0 = tile * 16;
        const int r0 = row0 + ar;
        const int r1 = r0 + 8;

        float c[8][8];
#pragma unroll
        for (int j = 0; j < 8; j++)
#pragma unroll
            for (int q = 0; q < 8; q++) c[j][q] = 0.f;

#pragma unroll
        for (int kk = 0; kk < 8; kk++) {
            float4 v0 = make_float4(0.f, 0.f, 0.f, 0.f), v1 = v0;
            if (r0 < N) v0 = __ldg(&A4[(size_t)r0 * 32 + kk * 4 + ac]);
            if (r1 < N) v1 = __ldg(&A4[(size_t)r1 * 32 + kk * 4 + ac]);
            if (applyRelu) {
                v0.x = fmaxf(v0.x, 0.f); v0.y = fmaxf(v0.y, 0.f);
                v0.z = fmaxf(v0.z, 0.f); v0.w = fmaxf(v0.w, 0.f);
                v1.x = fmaxf(v1.x, 0.f); v1.y = fmaxf(v1.y, 0.f);
                v1.z = fmaxf(v1.z, 0.f); v1.w = fmaxf(v1.w, 0.f);
            }
            // Frag assignment under sigma: a0<-v0.xy, a1<-v1.xy, a2<-v0.zw, a3<-v1.zw
            unsigned ah0, al0, ah1, al1, ah2, al2, ah3, al3;
            split2(v0.x, v0.y, ah0, al0);
            split2(v1.x, v1.y, ah1, al1);
            split2(v0.z, v0.w, ah2, al2);
            split2(v1.z, v1.w, ah3, al3);

            const unsigned kchunk = (unsigned)(((kk * 2 + b_half) ^ sw_b) << 4);
#pragma unroll
            for (int j = 0; j < 8; j++) {        // n16 groups
                const unsigned roff = (unsigned)((j * 16 + b_row_l) * 256) + kchunk;
                unsigned wh0, wh1, wh2, wh3, wl0, wl1, wl2, wl3;
                asm volatile("ldmatrix.sync.aligned.m8n8.x4.shared.b16 {%0,%1,%2,%3}, [%4];"
                             : "=r"(wh0), "=r"(wh1), "=r"(wh2), "=r"(wh3)
                             : "r"(sb + WHI + roff));
                asm volatile("ldmatrix.sync.aligned.m8n8.x4.shared.b16 {%0,%1,%2,%3}, [%4];"
                             : "=r"(wl0), "=r"(wl1), "=r"(wl2), "=r"(wl3)
                             : "r"(sb + WLO + roff));
                MMA_OP(c[j] + 0, ah0, ah1, ah2, ah3, wh0, wh1);
                MMA_OP(c[j] + 4, ah0, ah1, ah2, ah3, wh2, wh3);
                MMA_OP(c[j] + 0, al0, al1, al2, al3, wh0, wh1);
                MMA_OP(c[j] + 4, al0, al1, al2, al3, wh2, wh3);
                MMA_OP(c[j] + 0, ah0, ah1, ah2, ah3, wl0, wl1);
                MMA_OP(c[j] + 4, ah0, ah1, ah2, ah3, wl2, wl3);
            }
        }

        if (permuteStore) {
            // pi-permuted column order: one STG.128 per j per row.
            if (r0 < N) {
                float4* Crow = (float4*)(C + (size_t)r0 * 128) + (lane & 3);
#pragma unroll
                for (int j = 0; j < 8; j++)
                    Crow[j * 4] = make_float4(c[j][0], c[j][1], c[j][4], c[j][5]);
            }
            if (r1 < N) {
                float4* Crow = (float4*)(C + (size_t)r1 * 128) + (lane & 3);
#pragma unroll
                for (int j = 0; j < 8; j++)
                    Crow[j * 4] = make_float4(c[j][2], c[j][3], c[j][6], c[j][7]);
            }
        } else {
            if (r0 < N) {
                float* Crow = C + (size_t)r0 * 128 + (lane & 3) * 2;
#pragma unroll
                for (int j = 0; j < 8; j++) {
                    *(float2*)(Crow + j * 16) = make_float2(c[j][0], c[j][1]);
                    *(float2*)(Crow + j * 16 + 8) = make_float2(c[j][4], c[j][5]);
                }
            }
            if (r1 < N) {
                float* Crow = C + (size_t)r1 * 128 + (lane & 3) * 2;
#pragma unroll
                for (int j = 0; j < 8; j++) {
                    *(float2*)(Crow + j * 16) = make_float2(c[j][2], c[j][3]);
                    *(float2*)(Crow + j * 16 + 8) = make_float2(c[j][6], c[j][7]);
                }
            }
        }
    }
}

// ---------------------------------------------------------------------------
// Pull aggregation (R8 version, proven local optimum): one warp per node.
// Permutation-transparent: sums rows elementwise.
// ---------------------------------------------------------------------------
__global__ void aggregate_kernel(const float* __restrict__ m,
                                 const int* __restrict__ counts,
                                 const int* __restrict__ slots,
                                 const float* __restrict__ bias,
                                 float* __restrict__ out, int N, int zeroCounts) {
    int warp = (blockIdx.x * blockDim.x + threadIdx.x) >> 5;
    int lane = threadIdx.x & 31;
    if (warp >= N) return;
    int cnt = counts[warp];
    if (cnt > MAXDEG) cnt = MAXDEG;
    const int* sl = slots + (size_t)warp * MAXDEG;
    float4 acc = ((const float4*)bias)[lane];
    int idx = 0;
    for (; idx + 4 <= cnt; idx += 4) {
        int s0 = __ldg(&sl[idx]);
        int s1 = __ldg(&sl[idx + 1]);
        int s2 = __ldg(&sl[idx + 2]);
        int s3 = __ldg(&sl[idx + 3]);
        float4 v0 = ((const float4*)(m + (size_t)s0 * 128))[lane];
        float4 v1 = ((const float4*)(m + (size_t)s1 * 128))[lane];
        float4 v2 = ((const float4*)(m + (size_t)s2 * 128))[lane];
        float4 v3 = ((const float4*)(m + (size_t)s3 * 128))[lane];
        acc.x += v0.x + v1.x + v2.x + v3.x;
        acc.y += v0.y + v1.y + v2.y + v3.y;
        acc.z += v0.z + v1.z + v2.z + v3.z;
        acc.w += v0.w + v1.w + v2.w + v3.w;
    }
    for (; idx < cnt; idx++) {
        int s = __ldg(&sl[idx]);
        float4 v = ((const float4*)(m + (size_t)s * 128))[lane];
        acc.x += v.x; acc.y += v.y; acc.z += v.z; acc.w += v.w;
    }
    ((float4*)(out + (size_t)warp * 128))[lane] = acc;
    if (zeroCounts && lane == 0) ((int*)counts)[warp] = 0;
}

// ---------------------------------------------------------------------------
extern "C" void kernel_launch(void* const* d_in, const int* in_sizes, int n_in,
                              void* d_out, int out_size) {
    const float* x  = (const float*)d_in[0];
    const int*   ei = (const int*)d_in[1];
    const float* W1 = (const float*)d_in[2];
    const float* b1 = (const float*)d_in[3];
    const float* W2 = (const float*)d_in[4];
    const float* b2 = (const float*)d_in[5];
    float* out = (float*)d_out;

    const int N = in_sizes[0] / 128;
    const int E = in_sizes[1] / 2;
    const int* src = ei;
    const int* dst = ei + E;

    float* gm; float* gh;
    int *counts, *slots, *tilectr;
    unsigned short *wthi, *wtlo;
    float* b1p;
    cudaGetSymbolAddress((void**)&gm, g_m);
    cudaGetSymbolAddress((void**)&gh, g_h);
    cudaGetSymbolAddress((void**)&counts, g_counts);
    cudaGetSymbolAddress((void**)&slots, g_slots);
    cudaGetSymbolAddress((void**)&wthi, g_wthi);
    cudaGetSymbolAddress((void**)&wtlo, g_wtlo);
    cudaGetSymbolAddress((void**)&b1p, g_b1p);
    cudaGetSymbolAddress((void**)&tilectr, g_tilectr);

    cudaFuncSetAttribute(gemm_mma, cudaFuncAttributeMaxDynamicSharedMemorySize, GEMM_SMEM);

    const int numTiles = (N + 15) / 16;
    const int gemmGrid = 296;                       // 2 CTA/SM persistent
    const int prepGrid = 128 + (E + 255) / 256;
    const int aggGrid = (N + 7) / 8;

    // Fused prep: W conversion (+sigma^{-1} for W1), b1 perm, slot table,
    // tile-counter reset (every replay).
    prep_kernel<<<prepGrid, 256>>>(W1, W2, b1, src, dst, counts, slots, E);

    // Layer 1: m (pi-permuted columns) = x @ W1; h_perm = agg(m) + b1p.
    gemm_mma<<<gemmGrid, 256, GEMM_SMEM>>>(x, wthi, wtlo, gm, N, 0, numTiles, 1, tilectr);
    aggregate_kernel<<<aggGrid, 256>>>(gm, counts, slots, b1p, gh, N, 0);

    // Layer 2: sigma-fragment load of h_perm cancels pi -> standard W2, standard store.
    gemm_mma<<<gemmGrid, 256, GEMM_SMEM>>>(gh, wthi + 128 * 128, wtlo + 128 * 128, gm, N, 1, numTiles, 0, tilectr + 1);
    aggregate_kernel<<<aggGrid, 256>>>(gm, counts, slots, b2, out, N, 1);
}